// round 6
// baseline (speedup 1.0000x reference)
#include <cuda_runtime.h>
#include <cuda_bf16.h>

// Problem constants
#define Bsz   4
#define NODES 51
#define MODAL 4
#define SEQ   256
#define DM    128
#define DK    64
#define NBN   (Bsz * NODES)          // 204
#define GRID_N 128                   // table nodes per (bn, j)

__device__ __forceinline__ float fast_exp2(float x) {
    float y;
    asm("ex2.approx.ftz.f32 %0, %1;" : "=f"(y) : "f"(x));
    return y;
}

// ---- packed f32x2 helpers ----
typedef unsigned long long u64;
__device__ __forceinline__ u64 pk2(float lo, float hi) {
    u64 r;
    asm("mov.b64 %0, {%1, %2};" : "=l"(r) : "f"(lo), "f"(hi));
    return r;
}
__device__ __forceinline__ void upk2(u64 p, float& lo, float& hi) {
    asm("mov.b64 {%0, %1}, %2;" : "=f"(lo), "=f"(hi) : "l"(p));
}
__device__ __forceinline__ u64 mul2(u64 a, u64 b) {
    u64 r;
    asm("mul.rn.f32x2 %0, %1, %2;" : "=l"(r) : "l"(a), "l"(b));
    return r;
}
__device__ __forceinline__ u64 fma2(u64 a, u64 b, u64 c) {
    u64 r;
    asm("fma.rn.f32x2 %0, %1, %2, %3;" : "=l"(r) : "l"(a), "l"(b), "l"(c));
    return r;
}
__device__ __forceinline__ u64 add2(u64 a, u64 b) {
    u64 r;
    asm("add.rn.f32x2 %0, %1, %2;" : "=l"(r) : "l"(a), "l"(b));
    return r;
}

// ---------------------------------------------------------------------------
// Single fused kernel. Block = bn (204 blocks x 1024 threads).
// Phase 1: load x tile (4KB) + per-warp min/max.
// Phase 2: redundantly compute A2,C2,Wm,Bm from L2-hot weights.
// Phase 3: tabulate f_j on a 128-node grid over the exact query range
//          (thread = (j, node, half-of-t); pair-combined via shfl).
// Phase 4: Catmull-Rom interpolation, one output per thread.
// ---------------------------------------------------------------------------
__global__ __launch_bounds__(1024, 2) void mmf_fused_kernel(
    const float* __restrict__ x,
    const float* __restrict__ Wq, const float* __restrict__ bq,
    const float* __restrict__ Wk,
    const float* __restrict__ Wv, const float* __restrict__ bv,
    float* __restrict__ out) {
    const int bn = blockIdx.x;
    const int tid = threadIdx.x;
    const int wid = tid >> 5;
    const int lane = tid & 31;

    __shared__ float4 sx4[MODAL][SEQ / 4];   // 4 KB x tile
    __shared__ float sF[MODAL][GRID_N];      // 2 KB table
    __shared__ float swk[DK];                // Wk row sums
    __shared__ float wredA[32], wredV[32];   // per-warp partials
    __shared__ float wmax[8], wmin[8];
    __shared__ float sc[4];                  // {A2, C2, Wm, Bm}
    __shared__ float sgrid[2];               // {a_lo, h}

    // ---- Phase 1: x tile + min/max (threads 0-255) ----
    if (tid < 256) {
        float4 v = ((const float4*)(x + (size_t)bn * (MODAL * SEQ)))[tid];
        sx4[0][tid] = *(&sx4[0][0] + tid, &v), ((float4*)sx4)[tid] = v;
        float mx = fmaxf(fmaxf(v.x, v.y), fmaxf(v.z, v.w));
        float mn = fminf(fminf(v.x, v.y), fminf(v.z, v.w));
#pragma unroll
        for (int off = 16; off; off >>= 1) {
            mx = fmaxf(mx, __shfl_xor_sync(0xffffffff, mx, off));
            mn = fminf(mn, __shfl_xor_sync(0xffffffff, mn, off));
        }
        if (lane == 0) { wmax[wid] = mx; wmin[wid] = mn; }
    }

    // ---- Phase 2a: wk row sums (16 threads per row, 8 elems each) ----
    {
        const int k   = tid >> 4;
        const int sub = tid & 15;
        const float4* p = (const float4*)(Wk + k * DM + sub * 8);
        float4 a = p[0], b = p[1];
        float s = ((a.x + a.y) + (a.z + a.w)) + ((b.x + b.y) + (b.z + b.w));
#pragma unroll
        for (int off = 8; off; off >>= 1) s += __shfl_xor_sync(0xffffffff, s, off);
        if (sub == 0) swk[k] = s;
    }
    __syncthreads();

    // ---- Phase 2b: A2 partial (Wq . wk) and Wv total ----
    {
        const int k   = tid >> 4;
        const int sub = tid & 15;
        const float4* pq = (const float4*)(Wq + k * DM + sub * 8);
        const float4* pv = (const float4*)(Wv + k * DM + sub * 8);
        float4 a = pq[0], b = pq[1];
        float4 c = pv[0], d = pv[1];
        float sq = ((a.x + a.y) + (a.z + a.w)) + ((b.x + b.y) + (b.z + b.w));
        float sv = ((c.x + c.y) + (c.z + c.w)) + ((d.x + d.y) + (d.z + d.w));
        float pa = sq * swk[k];
#pragma unroll
        for (int off = 16; off; off >>= 1) {
            pa += __shfl_xor_sync(0xffffffff, pa, off);
            sv += __shfl_xor_sync(0xffffffff, sv, off);
        }
        if (lane == 0) { wredA[wid] = pa; wredV[wid] = sv; }
    }
    __syncthreads();

    // ---- Phase 2c: finalize scalars (warp 0) + grid range (warp 1) ----
    if (wid == 0) {
        float pa = wredA[lane];
        float pv = wredV[lane];
        float pc = bq[lane] * swk[lane] + bq[lane + 32] * swk[lane + 32];
        float pb = bv[lane] + bv[lane + 32];
#pragma unroll
        for (int off = 16; off; off >>= 1) {
            pa += __shfl_xor_sync(0xffffffff, pa, off);
            pv += __shfl_xor_sync(0xffffffff, pv, off);
            pc += __shfl_xor_sync(0xffffffff, pc, off);
            pb += __shfl_xor_sync(0xffffffff, pb, off);
        }
        if (lane == 0) {
            const float K = 0.125f * 1.4426950408889634f;  // log2e/sqrt(64)
            sc[0] = pa * K;                                 // A2
            sc[1] = pc * K;                                 // C2
            sc[2] = pv * (1.0f / DK) * (1.0f / (MODAL - 1));  // Wm
            sc[3] = pb * (1.0f / DK);                       // Bm
        }
    } else if (wid == 1 && lane == 0) {
        float tmx = wmax[0], tmn = wmin[0];
#pragma unroll
        for (int k = 1; k < 8; k++) {
            tmx = fmaxf(tmx, wmax[k]);
            tmn = fminf(tmn, wmin[k]);
        }
        sgrid[0] = tmn;   // stash x-range; converted to a-range after sync
        sgrid[1] = tmx;
    }
    __syncthreads();

    const float A2 = sc[0];
    const float C2s = sc[1];
    {
        const float a_c1 = fmaf(A2, sgrid[0], C2s);
        const float a_c2 = fmaf(A2, sgrid[1], C2s);
        const float alo = fminf(a_c1, a_c2);
        const float ahi = fmaxf(a_c1, a_c2);
        // every thread computes the same values; no extra sync needed
        const float h = (ahi - alo) * (1.0f / (GRID_N - 1));

        // ---- Phase 3: tabulate. thread = (j, node g, half) ----
        const int j    = tid >> 8;             // warp-uniform
        const int g    = (tid >> 1) & (GRID_N - 1);
        const int half = tid & 1;

        const float ag = fmaf(h, (float)g, alo);
        const u64 a22 = pk2(ag, ag);

        u64 num01 = 0ull, num23 = 0ull;
        u64 den01 = 0ull, den23 = 0ull;
        const ulonglong2* __restrict__ row =
            (const ulonglong2*)&sx4[j][half * (SEQ / 8)];
#pragma unroll 8
        for (int t4 = 0; t4 < SEQ / 8; t4++) {    // 128 elements
            ulonglong2 xt = row[t4];
            u64 p01 = mul2(a22, xt.x);
            u64 p23 = mul2(a22, xt.y);
            float p0, p1, p2, p3;
            upk2(p01, p0, p1);
            upk2(p23, p2, p3);
            float e0 = fast_exp2(p0);
            float e1 = fast_exp2(p1);
            float e2 = fast_exp2(p2);
            float e3 = fast_exp2(p3);
            u64 e01 = pk2(e0, e1);
            u64 e23 = pk2(e2, e3);
            num01 = fma2(xt.x, e01, num01);
            num23 = fma2(xt.y, e23, num23);
            den01 = add2(den01, e01);
            den23 = add2(den23, e23);
        }
        float n0, n1, n2, n3, d0, d1, d2, d3;
        upk2(num01, n0, n1);
        upk2(num23, n2, n3);
        upk2(den01, d0, d1);
        upk2(den23, d2, d3);
        float num = (n0 + n1) + (n2 + n3);
        float den = (d0 + d1) + (d2 + d3);
        // combine the two halves (partner lane differs in bit 0)
        num += __shfl_xor_sync(0xffffffff, num, 1);
        den += __shfl_xor_sync(0xffffffff, den, 1);
        if (half == 0) sF[j][g] = __fdividef(num, den);

        if (tid == 0) {
            sgrid[0] = alo;
            sgrid[1] = (ahi > alo) ? (float)(GRID_N - 1) / (ahi - alo) : 0.0f;
        }
    }
    __syncthreads();

    // ---- Phase 4: interpolate. thread = (i, s) ----
    const int i = tid >> 8;

    const float xi = ((const float*)sx4)[tid];
    const float a2 = fmaf(A2, xi, C2s);
    const float alo  = sgrid[0];
    const float invh = sgrid[1];

    float u = (a2 - alo) * invh;
    int i1 = (int)floorf(u);
    i1 = max(0, min(GRID_N - 2, i1));
    float fr = fminf(fmaxf(u - (float)i1, 0.0f), 1.0f);
    const int im  = max(i1 - 1, 0);
    const int ip2 = min(i1 + 2, GRID_N - 1);

    float acc = 0.f;
#pragma unroll
    for (int j = 0; j < MODAL; j++) {
        if (j == i) continue;
        float p0 = sF[j][im];
        float p1 = sF[j][i1];
        float p2 = sF[j][i1 + 1];
        float p3 = sF[j][ip2];
        // Catmull-Rom
        float c3 = 3.0f * (p1 - p2) + (p3 - p0);
        float c2 = 2.0f * p0 - 5.0f * p1 + 4.0f * p2 - p3;
        float c1 = p2 - p0;
        float f = fmaf(0.5f * fr, fmaf(fr, fmaf(fr, c3, c2), c1), p1);
        acc += f;
    }

    out[(size_t)bn * (MODAL * SEQ) + tid] = fmaf(sc[2], acc, sc[3]);
}

// ---------------------------------------------------------------------------
// Launch
// ---------------------------------------------------------------------------
extern "C" void kernel_launch(void* const* d_in, const int* in_sizes, int n_in,
                              void* d_out, int out_size) {
    const float* x  = (const float*)d_in[0];
    const float* Wq = (const float*)d_in[1];
    const float* bq = (const float*)d_in[2];
    const float* Wk = (const float*)d_in[3];
    const float* Wv = (const float*)d_in[5];
    const float* bv = (const float*)d_in[6];
    float* out = (float*)d_out;

    mmf_fused_kernel<<<NBN, 1024>>>(x, Wq, bq, Wk, Wv, bv, out);
}